// round 1
// baseline (speedup 1.0000x reference)
#include <cuda_runtime.h>
#include <cstdint>

#define NROWS 256
#define DDIM  768
#define KD    128
#define NK    500
#define TK    4
#define RPB   4                 // rows per block
#define NBLK  (NROWS / RPB)     // 64 blocks

// output layout (float32, reference return order)
#define OC_OFF  0
#define IDX_OFF 786432
#define SC_OFF  787456
#define QP_OFF  788480

#define NEG_INF (-3.402823466e38f)

__device__ int g_topk_idx[NROWS * TK];

__device__ __forceinline__ bool better(float a, int ia, float b, int ib) {
    return (a > b) || (a == b && ia < ib);
}

// maintain sorted (desc by value, asc by index on ties) top-4 list in registers
__device__ __forceinline__ void insert4(float* v, int* id, float x, int ix) {
    if (!better(x, ix, v[3], id[3])) return;
    v[3] = x; id[3] = ix;
#pragma unroll
    for (int j = 3; j > 0; j--) {
        if (better(v[j], id[j], v[j - 1], id[j - 1])) {
            float tv = v[j]; v[j] = v[j - 1]; v[j - 1] = tv;
            int   ti = id[j]; id[j] = id[j - 1]; id[j - 1] = ti;
        }
    }
}

__global__ __launch_bounds__(256) void fused_kernel(
    const float* __restrict__ regs,
    const float* __restrict__ row_keys,
    const float* __restrict__ col_keys,
    const float* __restrict__ gamma,
    const float* __restrict__ beta,
    const float* __restrict__ Wq,
    const float* __restrict__ bq,
    const float* __restrict__ Wqc,
    const float* __restrict__ bqc,
    float* __restrict__ out)
{
    __shared__ __align__(16) float s_x[RPB][DDIM];     // 12 KB
    __shared__ __align__(16) float s_q[RPB][KD];       // 2 KB
    __shared__ float s_sc[2][RPB][NK];                 // 16 KB (row/col scores)
    __shared__ float s_part[2][RPB][KD];               // 4 KB (Q gemm partials)
    __shared__ float s_stat[RPB][2];
    __shared__ float s_tv[RPB][2][TK];
    __shared__ int   s_ti[RPB][2][TK];

    const int t    = threadIdx.x;
    const int warp = t >> 5;
    const int lane = t & 31;
    const int row0 = blockIdx.x * RPB;

    // ---- 1. load 4 input rows (768 float4) ----
    {
        const float4* src = (const float4*)(regs + (size_t)row0 * DDIM);
        float4* dst = (float4*)&s_x[0][0];
        for (int i = t; i < RPB * DDIM / 4; i += 256) dst[i] = src[i];
    }
    __syncthreads();

    // ---- 2. LayerNorm stats (one warp per row) ----
    if (warp < RPB) {
        const int r = warp;
        float s = 0.f;
        for (int j = lane; j < DDIM; j += 32) s += s_x[r][j];
#pragma unroll
        for (int o = 16; o; o >>= 1) s += __shfl_xor_sync(0xffffffffu, s, o);
        const float mu = s * (1.0f / DDIM);
        float vs = 0.f;
        for (int j = lane; j < DDIM; j += 32) { float dv = s_x[r][j] - mu; vs += dv * dv; }
#pragma unroll
        for (int o = 16; o; o >>= 1) vs += __shfl_xor_sync(0xffffffffu, vs, o);
        if (lane == 0) {
            s_stat[r][0] = mu;
            s_stat[r][1] = rsqrtf(vs * (1.0f / DDIM) + 1e-5f);
        }
    }
    __syncthreads();
    // normalize in place
    for (int i = t; i < RPB * DDIM; i += 256) {
        const int r = i / DDIM, d = i - r * DDIM;
        s_x[r][d] = (s_x[r][d] - s_stat[r][0]) * s_stat[r][1] * gamma[d] + beta[d];
    }
    __syncthreads();

    // ---- 3. queries = LN(x) @ Wq + bq  (split D across two thread halves) ----
    {
        const int k    = t & (KD - 1);
        const int half = t >> 7;
        float a0 = 0.f, a1 = 0.f, a2 = 0.f, a3 = 0.f;
        const float4* x0 = (const float4*)&s_x[0][0];
        const float4* x1 = (const float4*)&s_x[1][0];
        const float4* x2 = (const float4*)&s_x[2][0];
        const float4* x3 = (const float4*)&s_x[3][0];
        const int d4b = half * (DDIM / 8);   // 96 float4 per half
        const int d4e = d4b + (DDIM / 8);
        for (int d4 = d4b; d4 < d4e; d4++) {
            const int d = d4 * 4;
            const float w0 = Wq[(d + 0) * KD + k];
            const float w1 = Wq[(d + 1) * KD + k];
            const float w2 = Wq[(d + 2) * KD + k];
            const float w3 = Wq[(d + 3) * KD + k];
            float4 v;
            v = x0[d4]; a0 += v.x * w0 + v.y * w1 + v.z * w2 + v.w * w3;
            v = x1[d4]; a1 += v.x * w0 + v.y * w1 + v.z * w2 + v.w * w3;
            v = x2[d4]; a2 += v.x * w0 + v.y * w1 + v.z * w2 + v.w * w3;
            v = x3[d4]; a3 += v.x * w0 + v.y * w1 + v.z * w2 + v.w * w3;
        }
        s_part[half][0][k] = a0;
        s_part[half][1][k] = a1;
        s_part[half][2][k] = a2;
        s_part[half][3][k] = a3;
    }
    __syncthreads();
    if (t < KD) {
        const float bb = bq[t];
#pragma unroll
        for (int r = 0; r < RPB; r++)
            s_q[r][t] = s_part[0][r][t] + s_part[1][r][t] + bb;
    }
    __syncthreads();

    // ---- 4. row/col scores: 2 * RPB * NK dot-64 products ----
    for (int task = t; task < 2 * RPB * NK; task += 256) {
        const int side = (task >= RPB * NK) ? 1 : 0;
        const int rem  = task - side * RPB * NK;
        const int r    = rem / NK;
        const int kk   = rem - r * NK;
        const float4* kp = (const float4*)((side ? col_keys : row_keys) + (size_t)kk * 64);
        const float4* qp = (const float4*)(&s_q[r][side * 64]);
        float acc = 0.f;
#pragma unroll
        for (int i = 0; i < 16; i++) {
            const float4 a = kp[i], b = qp[i];
            acc += a.x * b.x + a.y * b.y + a.z * b.z + a.w * b.w;
        }
        s_sc[side][r][kk] = acc;
    }
    __syncthreads();

    // ---- 5. per-row per-side top-4 (one warp per (row, side)) ----
    {
        const int side = warp & 1;
        const int r    = warp >> 1;
        float v[TK]; int id[TK];
#pragma unroll
        for (int j = 0; j < TK; j++) { v[j] = NEG_INF; id[j] = 0x7fffffff; }
        for (int kk = lane; kk < NK; kk += 32)
            insert4(v, id, s_sc[side][r][kk], kk);
#pragma unroll
        for (int off = 16; off >= 1; off >>= 1) {
            float ov[TK]; int oi[TK];
#pragma unroll
            for (int j = 0; j < TK; j++) {
                ov[j] = __shfl_down_sync(0xffffffffu, v[j], off);
                oi[j] = __shfl_down_sync(0xffffffffu, id[j], off);
            }
            if (lane < off) {
#pragma unroll
                for (int j = 0; j < TK; j++) insert4(v, id, ov[j], oi[j]);
            }
        }
        if (lane == 0) {
#pragma unroll
            for (int j = 0; j < TK; j++) { s_tv[r][side][j] = v[j]; s_ti[r][side][j] = id[j]; }
        }
    }
    __syncthreads();

    // ---- 6. combine 16 candidates -> final top-4 (value desc, flat idx asc) ----
    if (t < RPB) {
        const int r = t;
        float rv[TK], cv[TK]; int ri[TK], ci[TK];
#pragma unroll
        for (int j = 0; j < TK; j++) {
            rv[j] = s_tv[r][0][j]; ri[j] = s_ti[r][0][j];
            cv[j] = s_tv[r][1][j]; ci[j] = s_ti[r][1][j];
        }
        float bv[TK]; int bi[TK];
#pragma unroll
        for (int j = 0; j < TK; j++) { bv[j] = NEG_INF; bi[j] = 0x7fffffff; }
#pragma unroll
        for (int i = 0; i < TK; i++)
#pragma unroll
            for (int j = 0; j < TK; j++)
                insert4(bv, bi, rv[i] + cv[j], ri[i] * NK + ci[j]);
        const int grow = row0 + r;
#pragma unroll
        for (int n = 0; n < TK; n++) {
            out[SC_OFF  + grow * TK + n] = bv[n];
            out[IDX_OFF + grow * TK + n] = (float)bi[n];
            g_topk_idx[grow * TK + n]    = bi[n];
        }
    }

    // ---- 7. query_projected = q @ Wqc + bqc ----
    {
        const int o0 = t;  // cols o0, o0+256, o0+512
        float acc[3][RPB];
#pragma unroll
        for (int c = 0; c < 3; c++)
#pragma unroll
            for (int r = 0; r < RPB; r++) acc[c][r] = 0.f;
        for (int j = 0; j < KD; j++) {
            const float q0 = s_q[0][j], q1 = s_q[1][j], q2 = s_q[2][j], q3 = s_q[3][j];
            const float* wr = Wqc + (size_t)j * DDIM;
#pragma unroll
            for (int c = 0; c < 3; c++) {
                const float w = wr[o0 + c * 256];
                acc[c][0] += q0 * w; acc[c][1] += q1 * w;
                acc[c][2] += q2 * w; acc[c][3] += q3 * w;
            }
        }
#pragma unroll
        for (int c = 0; c < 3; c++) {
            const int o = o0 + c * 256;
            const float bb = bqc[o];
#pragma unroll
            for (int r = 0; r < RPB; r++)
                out[QP_OFF + (size_t)(row0 + r) * DDIM + o] = acc[c][r] + bb;
        }
    }
}

// gather concepts[topk_idx] -> output_concepts (1024 rows x 768 floats)
__global__ __launch_bounds__(192) void gather_kernel(
    const float* __restrict__ concepts, float* __restrict__ out)
{
    const int n   = blockIdx.x;          // 0..1023
    const int cid = g_topk_idx[n];
    const float4* src = (const float4*)(concepts + (size_t)cid * DDIM);
    float4*       dst = (float4*)(out + OC_OFF + (size_t)n * DDIM);
    dst[threadIdx.x] = src[threadIdx.x]; // 192 threads x 16B = 768 floats
}

extern "C" void kernel_launch(void* const* d_in, const int* in_sizes, int n_in,
                              void* d_out, int out_size) {
    const float* regs     = (const float*)d_in[0];
    const float* row_keys = (const float*)d_in[1];
    const float* col_keys = (const float*)d_in[2];
    const float* concepts = (const float*)d_in[3];
    const float* gamma    = (const float*)d_in[4];
    const float* beta     = (const float*)d_in[5];
    const float* Wq       = (const float*)d_in[6];
    const float* bq       = (const float*)d_in[7];
    const float* Wqc      = (const float*)d_in[8];
    const float* bqc      = (const float*)d_in[9];
    float* out = (float*)d_out;

    fused_kernel<<<NBLK, 256>>>(regs, row_keys, col_keys, gamma, beta,
                                Wq, bq, Wqc, bqc, out);
    gather_kernel<<<NROWS * TK, 192>>>(concepts, out);
}